// round 15
// baseline (speedup 1.0000x reference)
#include <cuda_runtime.h>
#include <cuda_bf16.h>
#include <cstdint>

#define NMAX 512
#define DDIM 128
#define TA 4
#define MARGIN_F 0.1f
#define THREADS 512
#define NW (THREADS / 32)
#define SIMP (NMAX + 4)   // padded sim stride

// Global accumulators (zero at load; last block resets each call so graph
// replays stay deterministic).
__device__ float        g_sum;
__device__ int          g_cnt;
__device__ unsigned int g_done;

union U2 { unsigned long long u; float2 f; };

// Packed dual-FMA (sm_10x): d.lo += a.lo*b.lo ; d.hi += a.hi*b.hi
__device__ __forceinline__ void ffma2(unsigned long long& d,
                                      unsigned long long a,
                                      unsigned long long b) {
    asm("fma.rn.f32x2 %0, %1, %2, %0;" : "+l"(d) : "l"(a), "l"(b));
}

// Block (g, h): anchors [g*TA, g*TA+TA), negatives restricted to row half h.
// Positives may lie anywhere; a dedicated warp-per-positive dot pass computes
// their sims. Each (a, pos, neg) triplet is counted exactly once chip-wide.
__global__ __launch_bounds__(THREADS, 2) void fused_triplet_kernel(
    const float* __restrict__ emb,
    const int*   __restrict__ labels_raw,
    float*       __restrict__ out,
    int n, int nblocks) {

    __shared__ float s_sim[TA][SIMP];
    __shared__ float s_psim[TA][NMAX];
    __shared__ float s_ainv[TA];
    __shared__ int   s_lab[NMAX];
    __shared__ short s_pos[TA][NMAX];
    __shared__ int   s_npos[TA];
    __shared__ int   s_oddor;
    __shared__ float s_bsum;
    __shared__ int   s_bcnt;

    const int t    = threadIdx.x;
    const int wid  = t >> 5;
    const int lane = t & 31;
    const int q    = lane >> 3;   // sub-row within warp (0..3); also anchor-unit block
    const int p    = lane & 7;    // unit-group position (0..7)
    const int g    = blockIdx.x >> 1;
    const int h    = blockIdx.x & 1;
    const int a0   = g * TA;
    const int hn   = (n + 1) >> 1;
    const int r0   = h * hn;
    const int r1   = (r0 + hn < n) ? (r0 + hn) : n;

    // --- anchor fragments: direct LDG, issued first (16 independent loads) ---
    const ulonglong2* embp = (const ulonglong2*)emb;   // 16B units, 32/row
    ulonglong2 A[TA][4];
    #pragma unroll
    for (int ar = 0; ar < TA; ar++) {
        int a = a0 + ar;
        if (a >= n) a = 0;                     // clamped; guarded by va later
        #pragma unroll
        for (int k = 0; k < 4; k++)
            A[ar][k] = __ldg(embp + (size_t)a * (DDIM / 4) + p + 8 * k);
    }

    // --- labels word t (single load; feeds both detection and s_lab) ---
    int wlab = (t < n) ? labels_raw[t] : 0;

    if (t == 0) { s_oddor = 0; s_bsum = 0.0f; s_bcnt = 0; }
    if (t < TA) s_npos[t] = 0;

    // dtype detect: OR of odd words (int64 -> hi words all zero)
    {
        int oddacc = (t & 1) ? wlab : 0;
        #pragma unroll
        for (int o = 16; o > 0; o >>= 1)
            oddacc |= __shfl_xor_sync(0xffffffffu, oddacc, o);
        if (lane == 0 && oddacc) atomicOr(&s_oddor, oddacc);
    }

    // warp 0: anchor inverse norms -> smem.
    // NOTE: lane (q,p) holds units {p+8k}; lanes sharing p hold IDENTICAL
    // units, so the reduction must be the 8-lane butterfly (o=4,2,1) over p
    // within a q-group — a 32-lane butterfly would overcount 4x.
    if (wid == 0) {
        unsigned long long s2[TA] = {0ull, 0ull, 0ull, 0ull};
        #pragma unroll
        for (int k = 0; k < 4; k++) {
            #pragma unroll
            for (int ar = 0; ar < TA; ar++) {
                ffma2(s2[ar], A[ar][k].x, A[ar][k].x);
                ffma2(s2[ar], A[ar][k].y, A[ar][k].y);
            }
        }
        float v0, v1, v2, v3;
        { U2 u; u.u = s2[0]; v0 = u.f.x + u.f.y; }
        { U2 u; u.u = s2[1]; v1 = u.f.x + u.f.y; }
        { U2 u; u.u = s2[2]; v2 = u.f.x + u.f.y; }
        { U2 u; u.u = s2[3]; v3 = u.f.x + u.f.y; }
        #pragma unroll
        for (int o = 4; o > 0; o >>= 1) {
            v0 += __shfl_xor_sync(0xffffffffu, v0, o);
            v1 += __shfl_xor_sync(0xffffffffu, v1, o);
            v2 += __shfl_xor_sync(0xffffffffu, v2, o);
            v3 += __shfl_xor_sync(0xffffffffu, v3, o);
        }
        if (lane == 0) {
            s_ainv[0] = 1.0f / sqrtf(v0);
            s_ainv[1] = 1.0f / sqrtf(v1);
            s_ainv[2] = 1.0f / sqrtf(v2);
            s_ainv[3] = 1.0f / sqrtf(v3);
        }
    }
    __syncthreads();   // [B1] oddor + ainv ready
    const bool is_i32 = (s_oddor != 0);
    if (t < n)
        s_lab[t] = is_i32 ? wlab : labels_raw[2 * t];

    float ainv0 = s_ainv[0], ainv1 = s_ainv[1],
          ainv2 = s_ainv[2], ainv3 = s_ainv[3];

    // ---- dot 4 rows' fragments against all anchors ----
    #define DOT4(E, nrm, d0, d1, d2, d3)                                   \
    {                                                                      \
        unsigned long long accN = 0ull, acc0 = 0ull, acc1 = 0ull,          \
                           acc2 = 0ull, acc3 = 0ull;                       \
        _Pragma("unroll")                                                  \
        for (int k = 0; k < 4; k++) {                                      \
            ffma2(accN, E[k].x, E[k].x);                                   \
            ffma2(accN, E[k].y, E[k].y);                                   \
            ffma2(acc0, E[k].x, A[0][k].x);                                \
            ffma2(acc0, E[k].y, A[0][k].y);                                \
            ffma2(acc1, E[k].x, A[1][k].x);                                \
            ffma2(acc1, E[k].y, A[1][k].y);                                \
            ffma2(acc2, E[k].x, A[2][k].x);                                \
            ffma2(acc2, E[k].y, A[2][k].y);                                \
            ffma2(acc3, E[k].x, A[3][k].x);                                \
            ffma2(acc3, E[k].y, A[3][k].y);                                \
        }                                                                  \
        U2 un; un.u = accN;                                                \
        U2 u0; u0.u = acc0;                                                \
        U2 u1; u1.u = acc1;                                                \
        U2 u2; u2.u = acc2;                                                \
        U2 u3; u3.u = acc3;                                                \
        nrm = un.f.x + un.f.y;                                             \
        d0  = u0.f.x + u0.f.y;                                             \
        d1  = u1.f.x + u1.f.y;                                             \
        d2  = u2.f.x + u2.f.y;                                             \
        d3  = u3.f.x + u3.f.y;                                             \
    }

    // --- main pass: this block's row half only, 4 rows/warp/iter ---
    if (n == NMAX) {
        #pragma unroll
        for (int it = 0; it < (NMAX / 2) / (NW * 4); it++) {
            const int row = r0 + wid * 4 + q + it * (NW * 4);
            const ulonglong2* rp = embp + (size_t)row * (DDIM / 4);

            ulonglong2 E[4];
            #pragma unroll
            for (int k = 0; k < 4; k++) E[k] = rp[p + 8 * k];

            float nrm, d0, d1, d2, d3;
            DOT4(E, nrm, d0, d1, d2, d3);

            #pragma unroll
            for (int o = 4; o > 0; o >>= 1) {
                nrm += __shfl_xor_sync(0xffffffffu, nrm, o);
                d0  += __shfl_xor_sync(0xffffffffu, d0, o);
                d1  += __shfl_xor_sync(0xffffffffu, d1, o);
                d2  += __shfl_xor_sync(0xffffffffu, d2, o);
                d3  += __shfl_xor_sync(0xffffffffu, d3, o);
            }

            float jinv = rsqrtf(nrm);
            if (p < TA) {
                float d  = (p == 0) ? d0 : (p == 1) ? d1 : (p == 2) ? d2 : d3;
                float ai = (p == 0) ? ainv0 : (p == 1) ? ainv1
                         : (p == 2) ? ainv2 : ainv3;
                s_sim[p][row] = d * ai * jinv;
            }
        }
    } else {
        for (int rb = r0 + wid * 4; rb < r1; rb += NW * 4) {
            const int row = rb + q;
            const bool rok = (row < r1);
            const ulonglong2* rp = embp + (size_t)row * (DDIM / 4);

            ulonglong2 E[4];
            #pragma unroll
            for (int k = 0; k < 4; k++) {
                if (rok) E[k] = rp[p + 8 * k];
                else     { E[k].x = 0ull; E[k].y = 0ull; }
            }

            float nrm, d0, d1, d2, d3;
            DOT4(E, nrm, d0, d1, d2, d3);

            #pragma unroll
            for (int o = 4; o > 0; o >>= 1) {
                nrm += __shfl_xor_sync(0xffffffffu, nrm, o);
                d0  += __shfl_xor_sync(0xffffffffu, d0, o);
                d1  += __shfl_xor_sync(0xffffffffu, d1, o);
                d2  += __shfl_xor_sync(0xffffffffu, d2, o);
                d3  += __shfl_xor_sync(0xffffffffu, d3, o);
            }

            float jinv = rsqrtf(nrm);
            if (rok && p < TA) {
                float d  = (p == 0) ? d0 : (p == 1) ? d1 : (p == 2) ? d2 : d3;
                float ai = (p == 0) ? ainv0 : (p == 1) ? ainv1
                         : (p == 2) ? ainv2 : ainv3;
                s_sim[p][row] = d * ai * jinv;
            }
        }
    }
    #undef DOT4
    __syncthreads();   // [B2] half-sim + labels complete

    // --- build positive lists for all TA anchors (full index range) ---
    int  la[TA];
    bool va[TA];
    #pragma unroll
    for (int ar = 0; ar < TA; ar++) {
        int a = a0 + ar;
        va[ar] = (a < n);
        la[ar] = va[ar] ? s_lab[a] : -1;
    }
    for (int j = t; j < n; j += THREADS) {
        int lj = s_lab[j];
        #pragma unroll
        for (int ar = 0; ar < TA; ar++) {
            if (va[ar] && lj == la[ar] && j != a0 + ar) {
                int idx = atomicAdd(&s_npos[ar], 1);
                s_pos[ar][idx] = (short)j;
            }
        }
    }
    __syncthreads();   // [B3] pos lists done

    int npos[TA];
    #pragma unroll
    for (int ar = 0; ar < TA; ar++) npos[ar] = s_npos[ar];

    // --- positive sims: warp-per-positive full-row dot (any half) ---
    // lane's unit index = (lane&7) + 8*(lane>>3) = lane, i.e. A[ar][q];
    // full 32-lane butterfly is correct here (each unit counted once).
    #pragma unroll
    for (int ar = 0; ar < TA; ar++) {
        for (int pi = wid; pi < npos[ar]; pi += NW) {
            int j = s_pos[ar][pi];
            ulonglong2 e = embp[(size_t)j * (DDIM / 4) + lane];
            unsigned long long acc = 0ull, accN = 0ull;
            ffma2(acc,  e.x, A[ar][q].x);
            ffma2(acc,  e.y, A[ar][q].y);
            ffma2(accN, e.x, e.x);
            ffma2(accN, e.y, e.y);
            U2 ud; ud.u = acc;
            U2 un; un.u = accN;
            float d  = ud.f.x + ud.f.y;
            float nm = un.f.x + un.f.y;
            #pragma unroll
            for (int o = 16; o > 0; o >>= 1) {
                d  += __shfl_xor_sync(0xffffffffu, d, o);
                nm += __shfl_xor_sync(0xffffffffu, nm, o);
            }
            if (lane == 0)
                s_psim[ar][pi] = d * s_ainv[ar] * rsqrtf(nm);
        }
    }
    __syncthreads();   // [B4] psim ready

    // --- negative sweep over THIS HALF only: 2 anchors x 1 column/thread ---
    float sum0 = 0.0f, sum1 = 0.0f;
    int   cnt0 = 0,    cnt1 = 0;
    {
        const int tcol = t & 255;
        const int ar0  = (t >> 8) * 2;   // 0 or 2
        const int ar1  = ar0 + 1;
        const int lA   = la[ar0];
        const int lB   = la[ar1];
        const bool vA  = va[ar0], vB = va[ar1];
        const int npA  = npos[ar0], npB = npos[ar1];

        for (int nj = r0 + tcol; nj < r1; nj += 256) {
            int lj = s_lab[nj];
            if (vA && lj != lA) {
                float sn = s_sim[ar0][nj] + MARGIN_F;
                int pi = 0;
                for (; pi + 1 < npA; pi += 2) {
                    float x0 = fmaxf(sn - s_psim[ar0][pi],     0.0f);
                    float x1 = fmaxf(sn - s_psim[ar0][pi + 1], 0.0f);
                    sum0 += x0; cnt0 += (x0 > 1e-16f) ? 1 : 0;
                    sum1 += x1; cnt1 += (x1 > 1e-16f) ? 1 : 0;
                }
                if (pi < npA) {
                    float x0 = fmaxf(sn - s_psim[ar0][pi], 0.0f);
                    sum0 += x0; cnt0 += (x0 > 1e-16f) ? 1 : 0;
                }
            }
            if (vB && lj != lB) {
                float sn = s_sim[ar1][nj] + MARGIN_F;
                int pi = 0;
                for (; pi + 1 < npB; pi += 2) {
                    float x0 = fmaxf(sn - s_psim[ar1][pi],     0.0f);
                    float x1 = fmaxf(sn - s_psim[ar1][pi + 1], 0.0f);
                    sum0 += x0; cnt0 += (x0 > 1e-16f) ? 1 : 0;
                    sum1 += x1; cnt1 += (x1 > 1e-16f) ? 1 : 0;
                }
                if (pi < npB) {
                    float x0 = fmaxf(sn - s_psim[ar1][pi], 0.0f);
                    sum0 += x0; cnt0 += (x0 > 1e-16f) ? 1 : 0;
                }
            }
        }
    }
    float sum = sum0 + sum1;
    int   cnt = cnt0 + cnt1;

    // --- block reduce: warp shfl + smem atomics ---
    #pragma unroll
    for (int o = 16; o > 0; o >>= 1) {
        sum += __shfl_xor_sync(0xffffffffu, sum, o);
        cnt += __shfl_xor_sync(0xffffffffu, cnt, o);
    }
    if (lane == 0) {
        atomicAdd(&s_bsum, sum);
        atomicAdd(&s_bcnt, cnt);
    }
    __syncthreads();   // [B5]

    // --- global reduce + last-block finalize ---
    if (t == 0) {
        atomicAdd(&g_sum, s_bsum);
        atomicAdd(&g_cnt, s_bcnt);
        __threadfence();
        unsigned int d = atomicAdd(&g_done, 1u);
        if (d == (unsigned int)(nblocks - 1)) {
            float fs = g_sum;
            float fc = (float)g_cnt;
            out[0] = fs / (fc + 1e-16f);
            g_sum  = 0.0f;
            g_cnt  = 0;
            __threadfence();
            g_done = 0u;
        }
    }
}

extern "C" void kernel_launch(void* const* d_in, const int* in_sizes, int n_in,
                              void* d_out, int out_size) {
    const float* emb    = (const float*)d_in[0];
    const int*   labels = (const int*)d_in[1];
    float*       out    = (float*)d_out;

    int n = in_sizes[1];
    if (n > NMAX) n = NMAX;

    int nblocks = 2 * ((n + TA - 1) / TA);   // (anchor group, half) pairs
    fused_triplet_kernel<<<nblocks, THREADS>>>(emb, labels, out, n, nblocks);
}

// round 16
// speedup vs baseline: 1.5092x; 1.5092x over previous
#include <cuda_runtime.h>
#include <cuda_bf16.h>
#include <cstdint>

#define NMAX 512
#define DDIM 128
#define TA 4
#define MARGIN_F 0.1f
#define THREADS 256
#define NW (THREADS / 32)
#define SIMP (NMAX + 4)   // padded sim stride

// Global accumulators (zero at load; last block resets each call so graph
// replays stay deterministic).
__device__ float        g_sum;
__device__ int          g_cnt;
__device__ unsigned int g_done;

union U2 { unsigned long long u; float2 f; };

// Packed dual-FMA (sm_10x): d.lo += a.lo*b.lo ; d.hi += a.hi*b.hi
__device__ __forceinline__ void ffma2(unsigned long long& d,
                                      unsigned long long a,
                                      unsigned long long b) {
    asm("fma.rn.f32x2 %0, %1, %2, %0;" : "+l"(d) : "l"(a), "l"(b));
}

// Block (g, h): anchors [g*TA, g*TA+TA), negatives restricted to row half h.
// Positives may lie anywhere; a warp-per-positive dot pass computes their
// sims. Each (a, pos, neg) triplet is counted exactly once chip-wide.
// 256 threads @ 2 blocks/SM -> 128-reg cap: fits the ~120-reg main loop
// without the spills that killed the 512-thread/64-reg variant.
__global__ __launch_bounds__(THREADS, 2) void fused_triplet_kernel(
    const float* __restrict__ emb,
    const int*   __restrict__ labels_raw,
    float*       __restrict__ out,
    int n, int nblocks) {

    __shared__ float s_sim[TA][SIMP];
    __shared__ float s_psim[TA][NMAX];
    __shared__ float s_ainv[TA];
    __shared__ int   s_lab[NMAX];
    __shared__ short s_pos[TA][NMAX];
    __shared__ int   s_npos[TA];
    __shared__ int   s_oddor;
    __shared__ float s_bsum;
    __shared__ int   s_bcnt;

    const int t    = threadIdx.x;
    const int wid  = t >> 5;
    const int lane = t & 31;
    const int q    = lane >> 3;   // sub-row within warp (0..3); anchor-unit block
    const int p    = lane & 7;    // unit-group position (0..7)
    const int g    = blockIdx.x >> 1;
    const int h    = blockIdx.x & 1;
    const int a0   = g * TA;
    const int hn   = (n + 1) >> 1;
    const int r0   = h * hn;
    const int r1   = (r0 + hn < n) ? (r0 + hn) : n;

    // --- anchor fragments: direct LDG, issued first (16 independent loads) ---
    const ulonglong2* embp = (const ulonglong2*)emb;   // 16B units, 32/row
    ulonglong2 A[TA][4];
    #pragma unroll
    for (int ar = 0; ar < TA; ar++) {
        int a = a0 + ar;
        if (a >= n) a = 0;                     // clamped; guarded by va later
        #pragma unroll
        for (int k = 0; k < 4; k++)
            A[ar][k] = __ldg(embp + (size_t)a * (DDIM / 4) + p + 8 * k);
    }

    if (t == 0) { s_oddor = 0; s_bsum = 0.0f; s_bcnt = 0; }
    if (t < TA) s_npos[t] = 0;

    // dtype detect: OR of odd int32 words (int64 -> hi words all zero)
    {
        int oddacc = 0;
        for (int j = t; j < n; j += THREADS)
            if (j & 1) oddacc |= labels_raw[j];
        #pragma unroll
        for (int o = 16; o > 0; o >>= 1)
            oddacc |= __shfl_xor_sync(0xffffffffu, oddacc, o);
        if (lane == 0 && oddacc) atomicOr(&s_oddor, oddacc);
    }

    // warp 0: anchor inverse norms -> smem.
    // lane (q,p) holds units {p+8k}; lanes sharing p hold IDENTICAL units,
    // so reduce with the 8-lane butterfly (o=4,2,1) — 32-lane would 4x-count.
    if (wid == 0) {
        unsigned long long s2[TA] = {0ull, 0ull, 0ull, 0ull};
        #pragma unroll
        for (int k = 0; k < 4; k++) {
            #pragma unroll
            for (int ar = 0; ar < TA; ar++) {
                ffma2(s2[ar], A[ar][k].x, A[ar][k].x);
                ffma2(s2[ar], A[ar][k].y, A[ar][k].y);
            }
        }
        float v0, v1, v2, v3;
        { U2 u; u.u = s2[0]; v0 = u.f.x + u.f.y; }
        { U2 u; u.u = s2[1]; v1 = u.f.x + u.f.y; }
        { U2 u; u.u = s2[2]; v2 = u.f.x + u.f.y; }
        { U2 u; u.u = s2[3]; v3 = u.f.x + u.f.y; }
        #pragma unroll
        for (int o = 4; o > 0; o >>= 1) {
            v0 += __shfl_xor_sync(0xffffffffu, v0, o);
            v1 += __shfl_xor_sync(0xffffffffu, v1, o);
            v2 += __shfl_xor_sync(0xffffffffu, v2, o);
            v3 += __shfl_xor_sync(0xffffffffu, v3, o);
        }
        if (lane == 0) {
            s_ainv[0] = 1.0f / sqrtf(v0);
            s_ainv[1] = 1.0f / sqrtf(v1);
            s_ainv[2] = 1.0f / sqrtf(v2);
            s_ainv[3] = 1.0f / sqrtf(v3);
        }
    }
    __syncthreads();   // [B1] oddor + ainv ready
    const bool is_i32 = (s_oddor != 0);
    for (int j = t; j < n; j += THREADS)
        s_lab[j] = is_i32 ? labels_raw[j] : labels_raw[2 * j];

    float ainv0 = s_ainv[0], ainv1 = s_ainv[1],
          ainv2 = s_ainv[2], ainv3 = s_ainv[3];

    // ---- dot 4 rows' fragments against all anchors ----
    #define DOT4(E, nrm, d0, d1, d2, d3)                                   \
    {                                                                      \
        unsigned long long accN = 0ull, acc0 = 0ull, acc1 = 0ull,          \
                           acc2 = 0ull, acc3 = 0ull;                       \
        _Pragma("unroll")                                                  \
        for (int k = 0; k < 4; k++) {                                      \
            ffma2(accN, E[k].x, E[k].x);                                   \
            ffma2(accN, E[k].y, E[k].y);                                   \
            ffma2(acc0, E[k].x, A[0][k].x);                                \
            ffma2(acc0, E[k].y, A[0][k].y);                                \
            ffma2(acc1, E[k].x, A[1][k].x);                                \
            ffma2(acc1, E[k].y, A[1][k].y);                                \
            ffma2(acc2, E[k].x, A[2][k].x);                                \
            ffma2(acc2, E[k].y, A[2][k].y);                                \
            ffma2(acc3, E[k].x, A[3][k].x);                                \
            ffma2(acc3, E[k].y, A[3][k].y);                                \
        }                                                                  \
        U2 un; un.u = accN;                                                \
        U2 u0; u0.u = acc0;                                                \
        U2 u1; u1.u = acc1;                                                \
        U2 u2; u2.u = acc2;                                                \
        U2 u3; u3.u = acc3;                                                \
        nrm = un.f.x + un.f.y;                                             \
        d0  = u0.f.x + u0.f.y;                                             \
        d1  = u1.f.x + u1.f.y;                                             \
        d2  = u2.f.x + u2.f.y;                                             \
        d3  = u3.f.x + u3.f.y;                                             \
    }

    // --- main pass: this block's row half, 8 rows/warp/iter (2 groups) ---
    if (n == NMAX) {
        #pragma unroll
        for (int it = 0; it < (NMAX / 2) / (NW * 8); it++) {
            const int rowA = r0 + wid * 8 + q + it * (NW * 8);
            const int rowB = rowA + 4;
            const ulonglong2* rpA = embp + (size_t)rowA * (DDIM / 4);
            const ulonglong2* rpB = embp + (size_t)rowB * (DDIM / 4);

            ulonglong2 EA[4], EB[4];
            #pragma unroll
            for (int k = 0; k < 4; k++) EA[k] = rpA[p + 8 * k];
            #pragma unroll
            for (int k = 0; k < 4; k++) EB[k] = rpB[p + 8 * k];

            float nrmA, a_d0, a_d1, a_d2, a_d3;
            float nrmB, b_d0, b_d1, b_d2, b_d3;
            DOT4(EA, nrmA, a_d0, a_d1, a_d2, a_d3);
            DOT4(EB, nrmB, b_d0, b_d1, b_d2, b_d3);

            #pragma unroll
            for (int o = 4; o > 0; o >>= 1) {
                nrmA += __shfl_xor_sync(0xffffffffu, nrmA, o);
                nrmB += __shfl_xor_sync(0xffffffffu, nrmB, o);
                a_d0 += __shfl_xor_sync(0xffffffffu, a_d0, o);
                b_d0 += __shfl_xor_sync(0xffffffffu, b_d0, o);
                a_d1 += __shfl_xor_sync(0xffffffffu, a_d1, o);
                b_d1 += __shfl_xor_sync(0xffffffffu, b_d1, o);
                a_d2 += __shfl_xor_sync(0xffffffffu, a_d2, o);
                b_d2 += __shfl_xor_sync(0xffffffffu, b_d2, o);
                a_d3 += __shfl_xor_sync(0xffffffffu, a_d3, o);
                b_d3 += __shfl_xor_sync(0xffffffffu, b_d3, o);
            }

            float jinvA = rsqrtf(nrmA);
            float jinvB = rsqrtf(nrmB);
            if (p < TA) {
                float dA = (p == 0) ? a_d0 : (p == 1) ? a_d1
                         : (p == 2) ? a_d2 : a_d3;
                float dB = (p == 0) ? b_d0 : (p == 1) ? b_d1
                         : (p == 2) ? b_d2 : b_d3;
                float ai = (p == 0) ? ainv0 : (p == 1) ? ainv1
                         : (p == 2) ? ainv2 : ainv3;
                s_sim[p][rowA] = dA * ai * jinvA;
                s_sim[p][rowB] = dB * ai * jinvB;
            }
        }
    } else {
        for (int rb = r0 + wid * 4; rb < r1; rb += NW * 4) {
            const int row = rb + q;
            const bool rok = (row < r1);
            const ulonglong2* rp = embp + (size_t)row * (DDIM / 4);

            ulonglong2 E[4];
            #pragma unroll
            for (int k = 0; k < 4; k++) {
                if (rok) E[k] = rp[p + 8 * k];
                else     { E[k].x = 0ull; E[k].y = 0ull; }
            }

            float nrm, d0, d1, d2, d3;
            DOT4(E, nrm, d0, d1, d2, d3);

            #pragma unroll
            for (int o = 4; o > 0; o >>= 1) {
                nrm += __shfl_xor_sync(0xffffffffu, nrm, o);
                d0  += __shfl_xor_sync(0xffffffffu, d0, o);
                d1  += __shfl_xor_sync(0xffffffffu, d1, o);
                d2  += __shfl_xor_sync(0xffffffffu, d2, o);
                d3  += __shfl_xor_sync(0xffffffffu, d3, o);
            }

            float jinv = rsqrtf(nrm);
            if (rok && p < TA) {
                float d  = (p == 0) ? d0 : (p == 1) ? d1 : (p == 2) ? d2 : d3;
                float ai = (p == 0) ? ainv0 : (p == 1) ? ainv1
                         : (p == 2) ? ainv2 : ainv3;
                s_sim[p][row] = d * ai * jinv;
            }
        }
    }
    #undef DOT4
    __syncthreads();   // [B2] half-sim + labels complete

    // --- build positive lists for all TA anchors (full index range) ---
    int  la[TA];
    bool va[TA];
    #pragma unroll
    for (int ar = 0; ar < TA; ar++) {
        int a = a0 + ar;
        va[ar] = (a < n);
        la[ar] = va[ar] ? s_lab[a] : -1;
    }
    for (int j = t; j < n; j += THREADS) {
        int lj = s_lab[j];
        #pragma unroll
        for (int ar = 0; ar < TA; ar++) {
            if (va[ar] && lj == la[ar] && j != a0 + ar) {
                int idx = atomicAdd(&s_npos[ar], 1);
                s_pos[ar][idx] = (short)j;
            }
        }
    }
    __syncthreads();   // [B3] pos lists done

    int npos[TA];
    #pragma unroll
    for (int ar = 0; ar < TA; ar++) npos[ar] = s_npos[ar];

    // --- positive sims: warp-per-positive full-row dot (any half) ---
    // lane's unit index = (lane&7) + 8*(lane>>3) = lane, i.e. A[ar][q];
    // full 32-lane butterfly is correct here (each unit counted once).
    #pragma unroll
    for (int ar = 0; ar < TA; ar++) {
        for (int pi = wid; pi < npos[ar]; pi += NW) {
            int j = s_pos[ar][pi];
            ulonglong2 e = embp[(size_t)j * (DDIM / 4) + lane];
            unsigned long long acc = 0ull, accN = 0ull;
            ffma2(acc,  e.x, A[ar][q].x);
            ffma2(acc,  e.y, A[ar][q].y);
            ffma2(accN, e.x, e.x);
            ffma2(accN, e.y, e.y);
            U2 ud; ud.u = acc;
            U2 un; un.u = accN;
            float d  = ud.f.x + ud.f.y;
            float nm = un.f.x + un.f.y;
            #pragma unroll
            for (int o = 16; o > 0; o >>= 1) {
                d  += __shfl_xor_sync(0xffffffffu, d, o);
                nm += __shfl_xor_sync(0xffffffffu, nm, o);
            }
            if (lane == 0)
                s_psim[ar][pi] = d * s_ainv[ar] * rsqrtf(nm);
        }
    }
    __syncthreads();   // [B4] psim ready

    // --- negative sweep over THIS HALF only: 2 anchors x cols/thread ---
    float sum0 = 0.0f, sum1 = 0.0f;
    int   cnt0 = 0,    cnt1 = 0;
    {
        const int tcol = t & 127;
        const int ar0  = (t >> 7) * 2;   // 0 or 2
        const int ar1  = ar0 + 1;
        const int lA   = la[ar0];
        const int lB   = la[ar1];
        const bool vA  = va[ar0], vB = va[ar1];
        const int npA  = npos[ar0], npB = npos[ar1];

        for (int nj = r0 + tcol; nj < r1; nj += 128) {
            int lj = s_lab[nj];
            if (vA && lj != lA) {
                float sn = s_sim[ar0][nj] + MARGIN_F;
                int pi = 0;
                for (; pi + 1 < npA; pi += 2) {
                    float x0 = fmaxf(sn - s_psim[ar0][pi],     0.0f);
                    float x1 = fmaxf(sn - s_psim[ar0][pi + 1], 0.0f);
                    sum0 += x0; cnt0 += (x0 > 1e-16f) ? 1 : 0;
                    sum1 += x1; cnt1 += (x1 > 1e-16f) ? 1 : 0;
                }
                if (pi < npA) {
                    float x0 = fmaxf(sn - s_psim[ar0][pi], 0.0f);
                    sum0 += x0; cnt0 += (x0 > 1e-16f) ? 1 : 0;
                }
            }
            if (vB && lj != lB) {
                float sn = s_sim[ar1][nj] + MARGIN_F;
                int pi = 0;
                for (; pi + 1 < npB; pi += 2) {
                    float x0 = fmaxf(sn - s_psim[ar1][pi],     0.0f);
                    float x1 = fmaxf(sn - s_psim[ar1][pi + 1], 0.0f);
                    sum0 += x0; cnt0 += (x0 > 1e-16f) ? 1 : 0;
                    sum1 += x1; cnt1 += (x1 > 1e-16f) ? 1 : 0;
                }
                if (pi < npB) {
                    float x0 = fmaxf(sn - s_psim[ar1][pi], 0.0f);
                    sum0 += x0; cnt0 += (x0 > 1e-16f) ? 1 : 0;
                }
            }
        }
    }
    float sum = sum0 + sum1;
    int   cnt = cnt0 + cnt1;

    // --- block reduce: warp shfl + smem atomics ---
    #pragma unroll
    for (int o = 16; o > 0; o >>= 1) {
        sum += __shfl_xor_sync(0xffffffffu, sum, o);
        cnt += __shfl_xor_sync(0xffffffffu, cnt, o);
    }
    if (lane == 0) {
        atomicAdd(&s_bsum, sum);
        atomicAdd(&s_bcnt, cnt);
    }
    __syncthreads();   // [B5]

    // --- global reduce + last-block finalize ---
    if (t == 0) {
        atomicAdd(&g_sum, s_bsum);
        atomicAdd(&g_cnt, s_bcnt);
        __threadfence();
        unsigned int d = atomicAdd(&g_done, 1u);
        if (d == (unsigned int)(nblocks - 1)) {
            float fs = g_sum;
            float fc = (float)g_cnt;
            out[0] = fs / (fc + 1e-16f);
            g_sum  = 0.0f;
            g_cnt  = 0;
            __threadfence();
            g_done = 0u;
        }
    }
}

extern "C" void kernel_launch(void* const* d_in, const int* in_sizes, int n_in,
                              void* d_out, int out_size) {
    const float* emb    = (const float*)d_in[0];
    const int*   labels = (const int*)d_in[1];
    float*       out    = (float*)d_out;

    int n = in_sizes[1];
    if (n > NMAX) n = NMAX;

    int nblocks = 2 * ((n + TA - 1) / TA);   // (anchor group, half) pairs
    fused_triplet_kernel<<<nblocks, THREADS>>>(emb, labels, out, n, nblocks);
}

// round 17
// speedup vs baseline: 1.9483x; 1.2909x over previous
#include <cuda_runtime.h>
#include <cuda_bf16.h>
#include <cstdint>

#define NMAX 512
#define DDIM 128
#define TA 4
#define MARGIN_F 0.1f
#define THREADS 512
#define NW (THREADS / 32)

// Global accumulators (zero at load; last block resets each call so graph
// replays stay deterministic).
__device__ float        g_sum;
__device__ int          g_cnt;
__device__ unsigned int g_done;

union U2 { unsigned long long u; float2 f; };

// Packed dual-FMA (sm_10x): d.lo += a.lo*b.lo ; d.hi += a.hi*b.hi
__device__ __forceinline__ void ffma2(unsigned long long& d,
                                      unsigned long long a,
                                      unsigned long long b) {
    asm("fma.rn.f32x2 %0, %1, %2, %0;" : "+l"(d) : "l"(a), "l"(b));
}

__global__ __launch_bounds__(THREADS, 1) void fused_triplet_kernel(
    const float* __restrict__ emb,
    const int*   __restrict__ labels_raw,
    float*       __restrict__ out,
    int n, int nblocks) {

    __shared__ __align__(16) float4 s_sim4[NMAX];   // [row] -> (sim a0..a3)
    __shared__ float s_psim[TA][NMAX];
    __shared__ int   s_lab[NMAX];
    __shared__ short s_pos[TA][NMAX];
    __shared__ int   s_npos[TA];
    __shared__ int   s_oddor;
    __shared__ float s_bsum;
    __shared__ int   s_bcnt;

    const int t    = threadIdx.x;
    const int wid  = t >> 5;
    const int lane = t & 31;
    const int q    = lane >> 3;   // sub-row within warp (0..3)
    const int p    = lane & 7;    // unit-group position (0..7)
    const int a0   = blockIdx.x * TA;

    // --- anchor fragments: direct LDG, issued first (16 independent loads) ---
    const ulonglong2* embp = (const ulonglong2*)emb;   // 16B units, 32/row
    ulonglong2 A[TA][4];
    #pragma unroll
    for (int ar = 0; ar < TA; ar++) {
        int a = a0 + ar;
        if (a >= n) a = 0;                     // clamped; guarded by va later
        #pragma unroll
        for (int k = 0; k < 4; k++)
            A[ar][k] = __ldg(embp + (size_t)a * (DDIM / 4) + p + 8 * k);
    }

    // --- labels word t (single load; feeds both detection and s_lab) ---
    int wlab = (t < n) ? labels_raw[t] : 0;

    if (t == 0) { s_oddor = 0; s_bsum = 0.0f; s_bcnt = 0; }
    if (t < TA) s_npos[t] = 0;

    // dtype detect: OR of odd words (int64 -> hi words all zero)
    {
        int oddacc = (t & 1) ? wlab : 0;
        #pragma unroll
        for (int o = 16; o > 0; o >>= 1)
            oddacc |= __shfl_xor_sync(0xffffffffu, oddacc, o);
        if (lane == 0 && oddacc) atomicOr(&s_oddor, oddacc);
    }

    // anchor inverse norms: 4 interleaved 3-level (8-lane) butterflies.
    // lanes sharing p hold identical units -> o=4,2,1 only.
    float ainv0, ainv1, ainv2, ainv3;
    {
        unsigned long long s2[TA] = {0ull, 0ull, 0ull, 0ull};
        #pragma unroll
        for (int k = 0; k < 4; k++) {
            #pragma unroll
            for (int ar = 0; ar < TA; ar++) {
                ffma2(s2[ar], A[ar][k].x, A[ar][k].x);
                ffma2(s2[ar], A[ar][k].y, A[ar][k].y);
            }
        }
        float v0, v1, v2, v3;
        { U2 u; u.u = s2[0]; v0 = u.f.x + u.f.y; }
        { U2 u; u.u = s2[1]; v1 = u.f.x + u.f.y; }
        { U2 u; u.u = s2[2]; v2 = u.f.x + u.f.y; }
        { U2 u; u.u = s2[3]; v3 = u.f.x + u.f.y; }
        #pragma unroll
        for (int o = 4; o > 0; o >>= 1) {
            v0 += __shfl_xor_sync(0xffffffffu, v0, o);
            v1 += __shfl_xor_sync(0xffffffffu, v1, o);
            v2 += __shfl_xor_sync(0xffffffffu, v2, o);
            v3 += __shfl_xor_sync(0xffffffffu, v3, o);
        }
        ainv0 = rsqrtf(v0);
        ainv1 = rsqrtf(v1);
        ainv2 = rsqrtf(v2);
        ainv3 = rsqrtf(v3);
    }

    __syncthreads();                  // s_oddor ready
    const bool is_i32 = (s_oddor != 0);
    if (t < n)
        s_lab[t] = is_i32 ? wlab : labels_raw[2 * t];

    // ---- helper macro: dot 4 rows' fragments against all anchors ----
    #define DOT4(E, nrm, d0, d1, d2, d3)                                   \
    {                                                                      \
        unsigned long long accN = 0ull, acc0 = 0ull, acc1 = 0ull,          \
                           acc2 = 0ull, acc3 = 0ull;                       \
        _Pragma("unroll")                                                  \
        for (int k = 0; k < 4; k++) {                                      \
            ffma2(accN, E[k].x, E[k].x);                                   \
            ffma2(accN, E[k].y, E[k].y);                                   \
            ffma2(acc0, E[k].x, A[0][k].x);                                \
            ffma2(acc0, E[k].y, A[0][k].y);                                \
            ffma2(acc1, E[k].x, A[1][k].x);                                \
            ffma2(acc1, E[k].y, A[1][k].y);                                \
            ffma2(acc2, E[k].x, A[2][k].x);                                \
            ffma2(acc2, E[k].y, A[2][k].y);                                \
            ffma2(acc3, E[k].x, A[3][k].x);                                \
            ffma2(acc3, E[k].y, A[3][k].y);                                \
        }                                                                  \
        U2 un; un.u = accN;                                                \
        U2 u0; u0.u = acc0;                                                \
        U2 u1; u1.u = acc1;                                                \
        U2 u2; u2.u = acc2;                                                \
        U2 u3; u3.u = acc3;                                                \
        nrm = un.f.x + un.f.y;                                             \
        d0  = u0.f.x + u0.f.y;                                             \
        d1  = u1.f.x + u1.f.y;                                             \
        d2  = u2.f.x + u2.f.y;                                             \
        d3  = u3.f.x + u3.f.y;                                             \
    }

    // --- main pass ---
    if (n == NMAX) {
        // fast path: 8 rows/warp/iter (two independent 4-row groups)
        #pragma unroll
        for (int it = 0; it < NMAX / (NW * 8); it++) {
            const int rowA = wid * 8 + q + it * (NW * 8);
            const int rowB = rowA + 4;
            const ulonglong2* rpA = embp + (size_t)rowA * (DDIM / 4);
            const ulonglong2* rpB = embp + (size_t)rowB * (DDIM / 4);

            ulonglong2 EA[4], EB[4];
            #pragma unroll
            for (int k = 0; k < 4; k++) EA[k] = rpA[p + 8 * k];
            #pragma unroll
            for (int k = 0; k < 4; k++) EB[k] = rpB[p + 8 * k];

            float nrmA, a_d0, a_d1, a_d2, a_d3;
            float nrmB, b_d0, b_d1, b_d2, b_d3;
            DOT4(EA, nrmA, a_d0, a_d1, a_d2, a_d3);
            DOT4(EB, nrmB, b_d0, b_d1, b_d2, b_d3);

            #pragma unroll
            for (int o = 4; o > 0; o >>= 1) {
                nrmA += __shfl_xor_sync(0xffffffffu, nrmA, o);
                nrmB += __shfl_xor_sync(0xffffffffu, nrmB, o);
                a_d0 += __shfl_xor_sync(0xffffffffu, a_d0, o);
                b_d0 += __shfl_xor_sync(0xffffffffu, b_d0, o);
                a_d1 += __shfl_xor_sync(0xffffffffu, a_d1, o);
                b_d1 += __shfl_xor_sync(0xffffffffu, b_d1, o);
                a_d2 += __shfl_xor_sync(0xffffffffu, a_d2, o);
                b_d2 += __shfl_xor_sync(0xffffffffu, b_d2, o);
                a_d3 += __shfl_xor_sync(0xffffffffu, a_d3, o);
                b_d3 += __shfl_xor_sync(0xffffffffu, b_d3, o);
            }

            float jinvA = rsqrtf(nrmA);
            float jinvB = rsqrtf(nrmB);
            if (p < TA) {
                float dA = (p == 0) ? a_d0 : (p == 1) ? a_d1
                         : (p == 2) ? a_d2 : a_d3;
                float dB = (p == 0) ? b_d0 : (p == 1) ? b_d1
                         : (p == 2) ? b_d2 : b_d3;
                float ai = (p == 0) ? ainv0 : (p == 1) ? ainv1
                         : (p == 2) ? ainv2 : ainv3;
                ((float*)&s_sim4[rowA])[p] = dA * ai * jinvA;
                ((float*)&s_sim4[rowB])[p] = dB * ai * jinvB;
            }
        }
    } else {
        // general path (n < NMAX): 4 rows/warp/iter
        for (int rb = wid * 4; rb < n; rb += NW * 4) {
            const int row = rb + q;
            const bool rok = (row < n);
            const ulonglong2* rp = embp + (size_t)row * (DDIM / 4);

            ulonglong2 E[4];
            #pragma unroll
            for (int k = 0; k < 4; k++) {
                if (rok) E[k] = rp[p + 8 * k];
                else     { E[k].x = 0ull; E[k].y = 0ull; }
            }

            float nrm, d0, d1, d2, d3;
            DOT4(E, nrm, d0, d1, d2, d3);

            #pragma unroll
            for (int o = 4; o > 0; o >>= 1) {
                nrm += __shfl_xor_sync(0xffffffffu, nrm, o);
                d0  += __shfl_xor_sync(0xffffffffu, d0, o);
                d1  += __shfl_xor_sync(0xffffffffu, d1, o);
                d2  += __shfl_xor_sync(0xffffffffu, d2, o);
                d3  += __shfl_xor_sync(0xffffffffu, d3, o);
            }

            float jinv = rsqrtf(nrm);
            if (rok && p < TA) {
                float d  = (p == 0) ? d0 : (p == 1) ? d1 : (p == 2) ? d2 : d3;
                float ai = (p == 0) ? ainv0 : (p == 1) ? ainv1
                         : (p == 2) ? ainv2 : ainv3;
                ((float*)&s_sim4[row])[p] = d * ai * jinv;
            }
        }
    }
    #undef DOT4
    __syncthreads();   // sim + labels complete

    // --- build positive lists for all TA anchors in one pass ---
    int  la[TA];
    bool va[TA];
    #pragma unroll
    for (int ar = 0; ar < TA; ar++) {
        int a = a0 + ar;
        va[ar] = (a < n);
        la[ar] = va[ar] ? s_lab[a] : -1;
    }
    for (int j = t; j < n; j += THREADS) {
        int lj = s_lab[j];
        #pragma unroll
        for (int ar = 0; ar < TA; ar++) {
            if (va[ar] && lj == la[ar] && j != a0 + ar) {
                int idx = atomicAdd(&s_npos[ar], 1);
                s_pos[ar][idx] = (short)j;
            }
        }
    }
    __syncthreads();

    int npos[TA];
    #pragma unroll
    for (int ar = 0; ar < TA; ar++) npos[ar] = s_npos[ar];

    // --- gather psim[ar][pi] = sim4[pos[pi]][ar] (kills pointer chase) ---
    for (int idx = t; idx < TA * NMAX; idx += THREADS) {
        int ar = idx >> 9;          // NMAX == 512
        int pi = idx & (NMAX - 1);
        if (pi < s_npos[ar])
            s_psim[ar][pi] = ((const float*)&s_sim4[s_pos[ar][pi]])[ar];
    }
    __syncthreads();

    // --- negative sweep: one LDS.128 per column, linear psim, dual accums ---
    float sum0 = 0.0f, sum1 = 0.0f;
    int   cnt0 = 0,    cnt1 = 0;
    for (int nj = t; nj < n; nj += THREADS) {
        int lj = s_lab[nj];
        float4 s4 = s_sim4[nj];
        float simv[TA] = {s4.x, s4.y, s4.z, s4.w};
        #pragma unroll
        for (int ar = 0; ar < TA; ar++) {
            if (va[ar] && lj != la[ar]) {
                float sn = simv[ar] + MARGIN_F;
                int np = npos[ar];
                int pi = 0;
                for (; pi + 1 < np; pi += 2) {
                    float r0 = fmaxf(sn - s_psim[ar][pi],     0.0f);
                    float r1 = fmaxf(sn - s_psim[ar][pi + 1], 0.0f);
                    sum0 += r0; cnt0 += (r0 > 1e-16f) ? 1 : 0;
                    sum1 += r1; cnt1 += (r1 > 1e-16f) ? 1 : 0;
                }
                if (pi < np) {
                    float r0 = fmaxf(sn - s_psim[ar][pi], 0.0f);
                    sum0 += r0; cnt0 += (r0 > 1e-16f) ? 1 : 0;
                }
            }
        }
    }
    float sum = sum0 + sum1;
    int   cnt = cnt0 + cnt1;

    // --- block reduce: warp shfl + smem atomics ---
    #pragma unroll
    for (int o = 16; o > 0; o >>= 1) {
        sum += __shfl_xor_sync(0xffffffffu, sum, o);
        cnt += __shfl_xor_sync(0xffffffffu, cnt, o);
    }
    if (lane == 0) {
        atomicAdd(&s_bsum, sum);
        atomicAdd(&s_bcnt, cnt);
    }
    __syncthreads();

    // --- global reduce + last-block finalize ---
    if (t == 0) {
        atomicAdd(&g_sum, s_bsum);
        atomicAdd(&g_cnt, s_bcnt);
        __threadfence();
        unsigned int d = atomicAdd(&g_done, 1u);
        if (d == (unsigned int)(nblocks - 1)) {
            float fs = g_sum;
            float fc = (float)g_cnt;
            out[0] = fs / (fc + 1e-16f);
            g_sum  = 0.0f;
            g_cnt  = 0;
            __threadfence();
            g_done = 0u;
        }
    }
}

extern "C" void kernel_launch(void* const* d_in, const int* in_sizes, int n_in,
                              void* d_out, int out_size) {
    const float* emb    = (const float*)d_in[0];
    const int*   labels = (const int*)d_in[1];
    float*       out    = (float*)d_out;

    int n = in_sizes[1];
    if (n > NMAX) n = NMAX;

    int nblocks = (n + TA - 1) / TA;
    fused_triplet_kernel<<<nblocks, THREADS>>>(emb, labels, out, n, nblocks);
}